// round 2
// baseline (speedup 1.0000x reference)
#include <cuda_runtime.h>
#include <cuda_bf16.h>
#include <cstdint>

// Problem constants
#define TT      524288
#define INLEN   64
#define NMEM    64
#define HID     128       // 2*NMEM
#define OUTLEN  32
#define CHUNK   128
#define NCH     (TT / CHUNK)   // 4096

// Scratch (device globals — allocation-free rule)
__device__ float g_a[TT * NMEM];        // 134 MB
__device__ float g_b[TT * NMEM];        // 134 MB
__device__ float g_cA[NCH * NMEM];      // per-chunk composed A
__device__ float g_cB[NCH * NMEM];      // per-chunk composed B
__device__ float g_pB[NCH * NMEM];      // exclusive-prefix B = z at chunk start

// ---------- packed f32x2 helpers ----------
__device__ __forceinline__ unsigned long long pk2(float lo, float hi) {
    unsigned long long r;
    asm("mov.b64 %0, {%1, %2};" : "=l"(r) : "f"(lo), "f"(hi));
    return r;
}
__device__ __forceinline__ void fma2(unsigned long long& d, unsigned long long a,
                                     unsigned long long b) {
    asm("fma.rn.f32x2 %0, %1, %2, %3;" : "=l"(d) : "l"(a), "l"(b), "l"(d));
}
__device__ __forceinline__ float2 unpk2(unsigned long long v) {
    float2 r;
    asm("mov.b64 {%0, %1}, %2;" : "=f"(r.x), "=f"(r.y) : "l"(v));
    return r;
}
__device__ __forceinline__ float sigmoidf_(float x) {
    return __fdividef(1.0f, 1.0f + __expf(-x));
}

// =====================================================================
// Phase 1: per chunk (128 rows): h = sigmoid(x@W1 + B1); a = l*r; b = 1-l;
// write a,b to gmem; compose chunk (A,B) and write to g_cA/g_cB.
// Block: 256 threads. smem: Xs[64][128] (x transposed), Ws[64][128], Hs[128][128]
// =====================================================================
__global__ __launch_bounds__(256) void phase1_kernel(
    const float* __restrict__ x, const float* __restrict__ W1,
    const float* __restrict__ B1) {
    extern __shared__ float sm[];
    float* Xs = sm;                    // 64*128
    float* Ws = sm + 64 * 128;         // 64*128
    float* Hs = sm + 2 * 64 * 128;     // 128*128
    __shared__ float b1s[HID];

    const int tid = threadIdx.x;
    const int c   = blockIdx.x;
    const float* xblk = x + (size_t)c * CHUNK * INLEN;

    // load W1 [64][128] straight (k-major already)
    for (int i = tid; i < 64 * 128 / 4; i += 256)
        ((float4*)Ws)[i] = ((const float4*)W1)[i];
    if (tid < HID) b1s[tid] = B1[tid];

    // load x chunk transposed into Xs[k][row]
    // f4 index: idx = i*256 + tid, row = idx & 127, kq = idx >> 7 (kq in 0..15)
#pragma unroll
    for (int i = 0; i < 8; i++) {
        int idx = i * 256 + tid;
        int row = idx & 127, kq = idx >> 7;
        float4 v = ((const float4*)xblk)[row * 16 + kq];
        Xs[(kq * 4 + 0) * 128 + row] = v.x;
        Xs[(kq * 4 + 1) * 128 + row] = v.y;
        Xs[(kq * 4 + 2) * 128 + row] = v.z;
        Xs[(kq * 4 + 3) * 128 + row] = v.w;
    }
    __syncthreads();

    // GEMM 128x128, K=64. Thread tile 8 rows x 8 cols, packed f32x2 over row pairs.
    const int tx = tid & 15;   // col group
    const int ty = tid >> 4;   // row group
    unsigned long long acc[4][8];
#pragma unroll
    for (int rp = 0; rp < 4; rp++)
#pragma unroll
        for (int j = 0; j < 8; j++) acc[rp][j] = 0ull;

#pragma unroll 2
    for (int k = 0; k < 64; k++) {
        const float4 a0 = *(const float4*)&Xs[k * 128 + ty * 8];
        const float4 a1 = *(const float4*)&Xs[k * 128 + ty * 8 + 4];
        const float4 b0 = *(const float4*)&Ws[k * 128 + tx * 8];
        const float4 b1v = *(const float4*)&Ws[k * 128 + tx * 8 + 4];
        unsigned long long ar[4];
        ar[0] = pk2(a0.x, a0.y);
        ar[1] = pk2(a0.z, a0.w);
        ar[2] = pk2(a1.x, a1.y);
        ar[3] = pk2(a1.z, a1.w);
        float bs8[8] = {b0.x, b0.y, b0.z, b0.w, b1v.x, b1v.y, b1v.z, b1v.w};
#pragma unroll
        for (int j = 0; j < 8; j++) {
            unsigned long long bd = pk2(bs8[j], bs8[j]);
            fma2(acc[0][j], ar[0], bd);
            fma2(acc[1][j], ar[1], bd);
            fma2(acc[2][j], ar[2], bd);
            fma2(acc[3][j], ar[3], bd);
        }
    }

    // epilogue: bias + sigmoid -> Hs
#pragma unroll
    for (int rp = 0; rp < 4; rp++) {
#pragma unroll
        for (int j = 0; j < 8; j++) {
            float2 v = unpk2(acc[rp][j]);
            int col = tx * 8 + j;
            int row = ty * 8 + rp * 2;
            float bb = b1s[col];
            Hs[row * 128 + col]       = sigmoidf_(v.x + bb);
            Hs[(row + 1) * 128 + col] = sigmoidf_(v.y + bb);
        }
    }
    __syncthreads();

    // write a,b to gmem (coalesced): layout [T][64]
    const size_t base = (size_t)c * CHUNK * NMEM;
#pragma unroll 4
    for (int i = tid; i < CHUNK * NMEM; i += 256) {
        int t = i >> 6, ch = i & 63;
        float l = Hs[t * 128 + ch];
        float r = Hs[t * 128 + ch + 64];
        g_a[base + i] = l * r;
        g_b[base + i] = 1.0f - l;
    }

    // chunk composition: P <- M_t o P for t ascending
    if (tid < NMEM) {
        float A = 1.0f, Bv = 0.0f;
#pragma unroll 8
        for (int t = 0; t < CHUNK; t++) {
            float l = Hs[t * 128 + tid];
            float r = Hs[t * 128 + tid + 64];
            float a = l * r;
            float b = 1.0f - l;
            Bv = a * Bv + b;
            A  = a * A;
        }
        g_cA[c * NMEM + tid] = A;
        g_cB[c * NMEM + tid] = Bv;
    }
}

// =====================================================================
// Phase 2: exclusive scan over 4096 chunk compositions. One block, 64 threads.
// g_pB[c] = B of composition of chunks 0..c-1 (== z at chunk start, since u0=0)
// =====================================================================
__global__ void phase2_kernel() {
    const int ch = threadIdx.x;   // 0..63
    float Bv = 0.0f;
#pragma unroll 8
    for (int c = 0; c < NCH; c++) {
        float cA = g_cA[c * NMEM + ch];
        float cB = g_cB[c * NMEM + ch];
        g_pB[c * NMEM + ch] = Bv;
        Bv = cA * Bv + cB;
    }
}

// =====================================================================
// Phase 3: per chunk: rebuild z rows from prefix + (a,b), then out = z@W2 + B2.
// Block: 256 threads. smem: As[128][64], Bs[128][64], Zs[128][65] (padded), W2s[64][32]
// =====================================================================
#define ZPAD 65
__global__ __launch_bounds__(256) void phase3_kernel(
    const float* __restrict__ W2, const float* __restrict__ B2,
    float* __restrict__ out) {
    extern __shared__ float sm[];
    float* As  = sm;                         // 128*64
    float* Bs  = As + 128 * 64;              // 128*64
    float* Zs  = Bs + 128 * 64;              // 128*65
    float* W2s = Zs + 128 * ZPAD;            // 64*32

    const int tid = threadIdx.x;
    const int c   = blockIdx.x;
    const size_t base = (size_t)c * CHUNK * NMEM;

    for (int i = tid; i < CHUNK * NMEM / 4; i += 256) {
        ((float4*)As)[i] = ((const float4*)(g_a + base))[i];
        ((float4*)Bs)[i] = ((const float4*)(g_b + base))[i];
    }
    for (int i = tid; i < 64 * 32 / 4; i += 256)
        ((float4*)W2s)[i] = ((const float4*)W2)[i];
    __syncthreads();

    // sequential local scan per channel: z_t stored BEFORE applying row t
    if (tid < NMEM) {
        float u = g_pB[c * NMEM + tid];
#pragma unroll 4
        for (int t = 0; t < CHUNK; t++) {
            Zs[t * ZPAD + tid] = u;
            u = As[t * NMEM + tid] * u + Bs[t * NMEM + tid];
        }
    }
    __syncthreads();

    // GEMM2: Zs[128][64] @ W2s[64][32]. Thread tile 4 rows x 4 cols.
    const int colg = (tid & 7) * 4;    // 0..28
    const int rowg = (tid >> 3) * 4;   // 0..124
    float acc[4][4];
#pragma unroll
    for (int i = 0; i < 4; i++)
#pragma unroll
        for (int j = 0; j < 4; j++) acc[i][j] = 0.0f;

#pragma unroll 4
    for (int k = 0; k < 64; k++) {
        float4 w = *(const float4*)&W2s[k * 32 + colg];
        float z0 = Zs[(rowg + 0) * ZPAD + k];
        float z1 = Zs[(rowg + 1) * ZPAD + k];
        float z2 = Zs[(rowg + 2) * ZPAD + k];
        float z3 = Zs[(rowg + 3) * ZPAD + k];
        acc[0][0] += z0 * w.x; acc[0][1] += z0 * w.y; acc[0][2] += z0 * w.z; acc[0][3] += z0 * w.w;
        acc[1][0] += z1 * w.x; acc[1][1] += z1 * w.y; acc[1][2] += z1 * w.z; acc[1][3] += z1 * w.w;
        acc[2][0] += z2 * w.x; acc[2][1] += z2 * w.y; acc[2][2] += z2 * w.z; acc[2][3] += z2 * w.w;
        acc[3][0] += z3 * w.x; acc[3][1] += z3 * w.y; acc[3][2] += z3 * w.z; acc[3][3] += z3 * w.w;
    }

    float b0 = B2[colg + 0], b1 = B2[colg + 1], b2 = B2[colg + 2], b3 = B2[colg + 3];
#pragma unroll
    for (int i = 0; i < 4; i++) {
        float4 o;
        o.x = acc[i][0] + b0;
        o.y = acc[i][1] + b1;
        o.z = acc[i][2] + b2;
        o.w = acc[i][3] + b3;
        size_t row = (size_t)c * CHUNK + rowg + i;
        *(float4*)&out[row * OUTLEN + colg] = o;
    }
}

// =====================================================================
extern "C" void kernel_launch(void* const* d_in, const int* in_sizes, int n_in,
                              void* d_out, int out_size) {
    const float* x  = (const float*)d_in[0];   // [T, 64]
    const float* W1 = (const float*)d_in[1];   // [64, 128]
    const float* B1 = (const float*)d_in[2];   // [1, 128]
    const float* W2 = (const float*)d_in[3];   // [64, 32]
    const float* B2 = (const float*)d_in[4];   // [1, 32]
    float* out = (float*)d_out;                // [T, 32]

    const int P1_SMEM = (2 * 64 * 128 + 128 * 128) * 4;              // 131072
    const int P3_SMEM = (2 * 128 * 64 + 128 * ZPAD + 64 * 32) * 4;   // 107008

    cudaFuncSetAttribute(phase1_kernel, cudaFuncAttributeMaxDynamicSharedMemorySize, P1_SMEM);
    cudaFuncSetAttribute(phase3_kernel, cudaFuncAttributeMaxDynamicSharedMemorySize, P3_SMEM);

    phase1_kernel<<<NCH, 256, P1_SMEM>>>(x, W1, B1);
    phase2_kernel<<<1, NMEM>>>();
    phase3_kernel<<<NCH, 256, P3_SMEM>>>(W2, B2, out);
}

// round 4
// speedup vs baseline: 2.7989x; 2.7989x over previous
#include <cuda_runtime.h>
#include <cuda_bf16.h>
#include <cstdint>

// Problem constants
#define TT      524288
#define INLEN   64
#define NMEM    64
#define HID     128       // 2*NMEM
#define OUTLEN  32
#define CHUNK   128
#define NCH     (TT / CHUNK)   // 4096

// Scratch (device globals — allocation-free rule)
__device__ float g_a[TT * NMEM];        // 134 MB
__device__ float g_b[TT * NMEM];        // 134 MB
__device__ float g_cA[NMEM * NCH];      // per-chunk composed A, CHANNEL-MAJOR [ch][c]
__device__ float g_cB[NMEM * NCH];      // per-chunk composed B, CHANNEL-MAJOR [ch][c]
__device__ float g_pB[NCH * NMEM];      // exclusive-prefix B = z at chunk start [c][ch]

// ---------- packed f32x2 helpers ----------
__device__ __forceinline__ unsigned long long pk2(float lo, float hi) {
    unsigned long long r;
    asm("mov.b64 %0, {%1, %2};" : "=l"(r) : "f"(lo), "f"(hi));
    return r;
}
__device__ __forceinline__ void fma2(unsigned long long& d, unsigned long long a,
                                     unsigned long long b) {
    asm("fma.rn.f32x2 %0, %1, %2, %3;" : "=l"(d) : "l"(a), "l"(b), "l"(d));
}
__device__ __forceinline__ float2 unpk2(unsigned long long v) {
    float2 r;
    asm("mov.b64 {%0, %1}, %2;" : "=f"(r.x), "=f"(r.y) : "l"(v));
    return r;
}
__device__ __forceinline__ float sigmoidf_(float x) {
    return __fdividef(1.0f, 1.0f + __expf(-x));
}

// =====================================================================
// Phase 1: per chunk (128 rows): h = sigmoid(x@W1 + B1); a = l*r; b = 1-l;
// write a,b to gmem; compose chunk (A,B) -> g_cA/g_cB (channel-major).
// 512 threads. GEMM tile: 4 rows x 8 cols per thread, f32x2 packed over COLUMN
// pairs so the W operand is a free register pair from the float4 load.
// =====================================================================
__global__ __launch_bounds__(512) void phase1_kernel(
    const float* __restrict__ x, const float* __restrict__ W1,
    const float* __restrict__ B1) {
    extern __shared__ float sm[];
    float* Xs = sm;                    // 64*128  (x transposed: [k][row])
    float* Ws = sm + 64 * 128;         // 64*128  ([k][col])
    float* Hs = sm + 2 * 64 * 128;     // 128*128 ([row][col])
    __shared__ float b1s[HID];
    __shared__ float QA[8 * NMEM], QB[8 * NMEM];

    const int tid = threadIdx.x;
    const int c   = blockIdx.x;
    const float* xblk = x + (size_t)c * CHUNK * INLEN;

    // load W1 [64][128] straight (k-major already): 2048 float4
    for (int i = tid; i < 2048; i += 512)
        ((float4*)Ws)[i] = ((const float4*)W1)[i];
    if (tid < HID) b1s[tid] = B1[tid];

    // load x chunk transposed into Xs[k][row]: 2048 float4 of source
#pragma unroll
    for (int i = 0; i < 4; i++) {
        int idx = i * 512 + tid;
        int row = idx & 127, kq = idx >> 7;
        float4 v = ((const float4*)xblk)[row * 16 + kq];
        Xs[(kq * 4 + 0) * 128 + row] = v.x;
        Xs[(kq * 4 + 1) * 128 + row] = v.y;
        Xs[(kq * 4 + 2) * 128 + row] = v.z;
        Xs[(kq * 4 + 3) * 128 + row] = v.w;
    }
    __syncthreads();

    // GEMM 128x128, K=64. Thread tile 4 rows x 8 cols. acc packs col pairs.
    const int tx = tid & 15;   // col group: cols tx*8 .. tx*8+7
    const int ty = tid >> 4;   // row group: rows ty*4 .. ty*4+3
    unsigned long long acc[4][4];
#pragma unroll
    for (int r = 0; r < 4; r++)
#pragma unroll
        for (int j = 0; j < 4; j++) acc[r][j] = 0ull;

#pragma unroll 8
    for (int k = 0; k < 64; k++) {
        const float4 xv = *(const float4*)&Xs[k * 128 + ty * 4];
        const float4 w0 = *(const float4*)&Ws[k * 128 + tx * 8];
        const float4 w1 = *(const float4*)&Ws[k * 128 + tx * 8 + 4];
        unsigned long long bp[4];
        bp[0] = pk2(w0.x, w0.y);
        bp[1] = pk2(w0.z, w0.w);
        bp[2] = pk2(w1.x, w1.y);
        bp[3] = pk2(w1.z, w1.w);
        unsigned long long ad[4];
        ad[0] = pk2(xv.x, xv.x);
        ad[1] = pk2(xv.y, xv.y);
        ad[2] = pk2(xv.z, xv.z);
        ad[3] = pk2(xv.w, xv.w);
#pragma unroll
        for (int r = 0; r < 4; r++) {
            fma2(acc[r][0], ad[r], bp[0]);
            fma2(acc[r][1], ad[r], bp[1]);
            fma2(acc[r][2], ad[r], bp[2]);
            fma2(acc[r][3], ad[r], bp[3]);
        }
    }

    // epilogue: bias + sigmoid -> Hs
#pragma unroll
    for (int r = 0; r < 4; r++) {
#pragma unroll
        for (int j = 0; j < 4; j++) {
            float2 v = unpk2(acc[r][j]);
            int row = ty * 4 + r;
            int col = tx * 8 + j * 2;
            Hs[row * 128 + col]     = sigmoidf_(v.x + b1s[col]);
            Hs[row * 128 + col + 1] = sigmoidf_(v.y + b1s[col + 1]);
        }
    }
    __syncthreads();

    // write a,b to gmem (coalesced): layout [T][64]
    const size_t base = (size_t)c * CHUNK * NMEM;
#pragma unroll 4
    for (int i = tid; i < CHUNK * NMEM; i += 512) {
        int t = i >> 6, ch = i & 63;
        float l = Hs[t * 128 + ch];
        float r = Hs[t * 128 + ch + 64];
        g_a[base + i] = l * r;
        g_b[base + i] = 1.0f - l;
    }

    // parallel chunk composition: 8 sub-segments of 16 rows per channel
    {
        int ch = tid & 63, q = tid >> 6;   // q in 0..7
        float A = 1.0f, Bv = 0.0f;
#pragma unroll
        for (int t = 0; t < 16; t++) {
            int row = q * 16 + t;
            float l = Hs[row * 128 + ch];
            float r = Hs[row * 128 + ch + 64];
            float a = l * r;
            float b = 1.0f - l;
            Bv = a * Bv + b;
            A *= a;
        }
        QA[q * NMEM + ch] = A;
        QB[q * NMEM + ch] = Bv;
    }
    __syncthreads();
    if (tid < NMEM) {
        float A = 1.0f, Bv = 0.0f;
#pragma unroll
        for (int q = 0; q < 8; q++) {
            float a = QA[q * NMEM + tid];
            float b = QB[q * NMEM + tid];
            Bv = a * Bv + b;
            A *= a;
        }
        g_cA[tid * NCH + c] = A;    // channel-major for phase2
        g_cB[tid * NCH + c] = Bv;
    }
}

// =====================================================================
// Phase 2: hierarchical exclusive scan over 4096 chunk compositions.
// 64 blocks (one per channel), 256 threads, 16 chunks per thread.
// =====================================================================
__global__ __launch_bounds__(256) void phase2_kernel() {
    __shared__ float cAs[NCH], cBs[NCH];
    __shared__ float SA[256], SB[256];
    const int ch  = blockIdx.x;
    const int tid = threadIdx.x;

    // coalesced load of this channel's 4096 aggregates
    for (int i = tid; i < NCH / 4; i += 256) {
        ((float4*)cAs)[i] = ((const float4*)(g_cA + (size_t)ch * NCH))[i];
        ((float4*)cBs)[i] = ((const float4*)(g_cB + (size_t)ch * NCH))[i];
    }
    __syncthreads();

    // each thread composes 16 consecutive chunks
    const int base = tid * 16;
    float A = 1.0f, Bv = 0.0f;
#pragma unroll
    for (int j = 0; j < 16; j++) {
        float a = cAs[base + j], b = cBs[base + j];
        Bv = a * Bv + b;
        A *= a;
    }
    SA[tid] = A; SB[tid] = Bv;
    __syncthreads();

    // Hillis-Steele inclusive scan over 256 segment aggregates
#pragma unroll
    for (int s = 1; s < 256; s <<= 1) {
        float ta = SA[tid], tb = SB[tid];
        float pa = 1.0f, pb = 0.0f;
        if (tid >= s) { pa = SA[tid - s]; pb = SB[tid - s]; }
        __syncthreads();
        if (tid >= s) { SA[tid] = ta * pa; SB[tid] = ta * pb + tb; }
        __syncthreads();
    }

    // replay: write exclusive prefixes (only B matters since u0 = 0)
    float PB = (tid > 0) ? SB[tid - 1] : 0.0f;
#pragma unroll
    for (int j = 0; j < 16; j++) {
        g_pB[(size_t)(base + j) * NMEM + ch] = PB;
        PB = cAs[base + j] * PB + cBs[base + j];
    }
}

// =====================================================================
// Phase 3: per chunk: rebuild z via parallel in-chunk scan, out = z@W2 + B2.
// 512 threads. Scan: (ch, q) threads, q in 0..7, 16 rows each.
// =====================================================================
#define ZPAD 65
__global__ __launch_bounds__(512) void phase3_kernel(
    const float* __restrict__ W2, const float* __restrict__ B2,
    float* __restrict__ out) {
    extern __shared__ float sm[];
    float* As  = sm;                         // 128*64
    float* Bs  = As + 128 * 64;              // 128*64
    float* Zs  = Bs + 128 * 64;              // 128*65
    float* W2s = Zs + 128 * ZPAD;            // 64*32
    __shared__ float QA[8 * NMEM], QB[8 * NMEM];
    __shared__ float pBs[NMEM];

    const int tid = threadIdx.x;
    const int c   = blockIdx.x;
    const size_t base = (size_t)c * CHUNK * NMEM;

    for (int i = tid; i < CHUNK * NMEM / 4; i += 512) {
        ((float4*)As)[i] = ((const float4*)(g_a + base))[i];
        ((float4*)Bs)[i] = ((const float4*)(g_b + base))[i];
    }
    for (int i = tid; i < 64 * 32 / 4; i += 512)
        ((float4*)W2s)[i] = ((const float4*)W2)[i];
    if (tid < NMEM) pBs[tid] = g_pB[(size_t)c * NMEM + tid];
    __syncthreads();

    // pass 1: compose 16-row sub-segments
    const int ch = tid & 63, q = tid >> 6;   // q in 0..7
    {
        float A = 1.0f, Bv = 0.0f;
#pragma unroll
        for (int t = 0; t < 16; t++) {
            int row = q * 16 + t;
            float a = As[row * NMEM + ch];
            float b = Bs[row * NMEM + ch];
            Bv = a * Bv + b;
            A *= a;
        }
        QA[q * NMEM + ch] = A;
        QB[q * NMEM + ch] = Bv;
    }
    __syncthreads();

    // pass 2: sub-segment starting value, then replay writing z
    {
        float u = pBs[ch];
#pragma unroll
        for (int j = 0; j < 7; j++)
            if (j < q) u = QA[j * NMEM + ch] * u + QB[j * NMEM + ch];
#pragma unroll
        for (int t = 0; t < 16; t++) {
            int row = q * 16 + t;
            Zs[row * ZPAD + ch] = u;
            u = As[row * NMEM + ch] * u + Bs[row * NMEM + ch];
        }
    }
    __syncthreads();

    // GEMM2: Zs[128][64] @ W2s[64][32]. Thread tile 2 rows x 4 cols.
    const int colg = (tid & 7) * 4;    // 0..28
    const int rowg = (tid >> 3) * 2;   // 0..126
    float acc[2][4];
#pragma unroll
    for (int i = 0; i < 2; i++)
#pragma unroll
        for (int j = 0; j < 4; j++) acc[i][j] = 0.0f;

#pragma unroll 8
    for (int k = 0; k < 64; k++) {
        float4 w = *(const float4*)&W2s[k * 32 + colg];
        float z0 = Zs[(rowg + 0) * ZPAD + k];
        float z1 = Zs[(rowg + 1) * ZPAD + k];
        acc[0][0] += z0 * w.x; acc[0][1] += z0 * w.y; acc[0][2] += z0 * w.z; acc[0][3] += z0 * w.w;
        acc[1][0] += z1 * w.x; acc[1][1] += z1 * w.y; acc[1][2] += z1 * w.z; acc[1][3] += z1 * w.w;
    }

    float b0 = B2[colg + 0], b1 = B2[colg + 1], b2 = B2[colg + 2], b3 = B2[colg + 3];
#pragma unroll
    for (int i = 0; i < 2; i++) {
        float4 o;
        o.x = acc[i][0] + b0;
        o.y = acc[i][1] + b1;
        o.z = acc[i][2] + b2;
        o.w = acc[i][3] + b3;
        size_t row = (size_t)c * CHUNK + rowg + i;
        *(float4*)&out[row * OUTLEN + colg] = o;
    }
}

// =====================================================================
extern "C" void kernel_launch(void* const* d_in, const int* in_sizes, int n_in,
                              void* d_out, int out_size) {
    const float* x  = (const float*)d_in[0];   // [T, 64]
    const float* W1 = (const float*)d_in[1];   // [64, 128]
    const float* B1 = (const float*)d_in[2];   // [1, 128]
    const float* W2 = (const float*)d_in[3];   // [64, 32]
    const float* B2 = (const float*)d_in[4];   // [1, 32]
    float* out = (float*)d_out;                // [T, 32]

    const int P1_SMEM = (2 * 64 * 128 + 128 * 128) * 4;              // 131072
    const int P3_SMEM = (2 * 128 * 64 + 128 * ZPAD + 64 * 32) * 4;   // 107008

    cudaFuncSetAttribute(phase1_kernel, cudaFuncAttributeMaxDynamicSharedMemorySize, P1_SMEM);
    cudaFuncSetAttribute(phase3_kernel, cudaFuncAttributeMaxDynamicSharedMemorySize, P3_SMEM);

    phase1_kernel<<<NCH, 512, P1_SMEM>>>(x, W1, B1);
    phase2_kernel<<<64, 256>>>();
    phase3_kernel<<<NCH, 512, P3_SMEM>>>(W2, B2, out);
}